// round 6
// baseline (speedup 1.0000x reference)
#include <cuda_runtime.h>
#include <math.h>

#define BATCH  2
#define KPATCH 1600
#define DDIM   1024
#define CCLS   256
#define NBOX   32
#define PGRID  40
#define TARGET 560
#define BN     (BATCH*NBOX)            /* 64 */
#define NROWS  (BATCH*KPATCH + CCLS)   /* 3456 norm rows */
#define ROWS_PER_BLK 4                 /* 2 warps per row, MLP=4 */
#define NORMBLKS (NROWS/ROWS_PER_BLK)  /* 864 */
#define ZEROBLKS 4                     /* 4*256*4 float4 = 16384 floats */
#define QSPLIT 8

// ---------------- scratch (static device globals; no allocation) ----------------
__device__ float g_fninv[BATCH*KPATCH];     // 1/||feats[b,k,:]||
__device__ float g_eninv[CCLS];             // 1/||emb[c,:]||
__device__ float g_vy[BN*PGRID];            // per-box summed weights (y axis)
__device__ float g_vx[BN*PGRID];            // per-box summed weights (x axis)
__device__ int   g_rect[BN*4];              // p0,p1,q0,q1 nonzero tap rectangle
__device__ float g_cntinv[BN];              // 1/(box pixel count)
__device__ float g_Qpart[QSPLIT*BN*DDIM];   // partial weighted feature sums

// Keys cubic, a = -0.5 (matches jax.image.resize 'bicubic'), fp32
__device__ __forceinline__ float cubicf(float x) {   // x >= 0
    if (x < 1.f) return ((1.5f*x - 2.5f)*x)*x + 1.f;
    if (x < 2.f) return ((-0.5f*x + 2.5f)*x - 4.f)*x + 2.f;
    return 0.f;
}

// ------- kernel 1: box taps + out-zeroing + half-row-per-warp L2 norms ---------
// Grid layout: [0,BN) box blocks, [BN,BN+ZEROBLKS) zero blocks, rest norm blocks.
// Box/zero first so their (serial-ish / store) work overlaps the norm wave.
__global__ void __launch_bounds__(256) normbox_kernel(
        const float* __restrict__ feats,
        const float* __restrict__ emb,
        const int* __restrict__ boxes,
        float* __restrict__ outz) {
    int blk  = blockIdx.x;
    int t    = threadIdx.x;
    int warp = t >> 5, lane = t & 31;

    if (blk >= BN + ZEROBLKS) {
        // ---- norm branch: 4 rows per block, 2 warps per row (half row each) ----
        int nb   = blk - (BN + ZEROBLKS);
        int row  = nb * ROWS_PER_BLK + (warp >> 1);
        int half = warp & 1;
        const float4* p4 = (row < BATCH*KPATCH)
                 ? (const float4*)(feats + (size_t)row * DDIM)
                 : (const float4*)(emb   + (size_t)(row - BATCH*KPATCH) * DDIM);
        p4 += half * 128;                      // 128 float4 per half-row
        float4 v[4];
        #pragma unroll
        for (int i = 0; i < 4; ++i) v[i] = p4[lane + 32*i];   // 4 independent LDG.128
        float ss = 0.f;
        #pragma unroll
        for (int i = 0; i < 4; ++i)
            ss += v[i].x*v[i].x + v[i].y*v[i].y + v[i].z*v[i].z + v[i].w*v[i].w;
        #pragma unroll
        for (int o = 16; o; o >>= 1) ss += __shfl_xor_sync(0xffffffffu, ss, o);
        __shared__ float ws[8];
        if (lane == 0) ws[warp] = ss;
        __syncthreads();
        if (t < ROWS_PER_BLK) {
            int r = nb * ROWS_PER_BLK + t;
            float inv = 1.0f / sqrtf(ws[2*t] + ws[2*t+1]);
            if (r < BATCH*KPATCH) g_fninv[r] = inv;
            else                  g_eninv[r - BATCH*KPATCH] = inv;
        }
    } else if (blk >= BN) {
        // ---- zero branch: zero the 64KB output (replaces memset node) ----
        int zb = blk - BN;
        float4 z = make_float4(0.f, 0.f, 0.f, 0.f);
        ((float4*)outz)[(zb * 256 + t) * 4 + 0] = z;
        ((float4*)outz)[(zb * 256 + t) * 4 + 1] = z;
        ((float4*)outz)[(zb * 256 + t) * 4 + 2] = z;
        ((float4*)outz)[(zb * 256 + t) * 4 + 3] = z;
    } else {
        // ---- box branch: one block per box; parallel over output pixels ----
        int bn = blk;
        int x_min = boxes[bn*4+0], y_min = boxes[bn*4+1];
        int x_max = boxes[bn*4+2], y_max = boxes[bn*4+3];

        __shared__ float sv[2*PGRID];          // svy[0..39], svx[40..79]
        if (t < 2*PGRID) sv[t] = 0.f;
        __syncthreads();

        int ny = y_max - 1 - y_min;            // pixels y_min .. y_max-2
        int nx = x_max - 1 - x_min;
        for (int i = t; i < ny + nx; i += 256) {
            int y; float* dst;
            if (i < ny) { y = y_min + i;        dst = sv; }
            else        { y = x_min + (i - ny); dst = sv + PGRID; }
            float sf = (y + 0.5f) * (1.0f/14.0f) - 0.5f;
            int i0 = (int)floorf(sf);
            float w[4]; float cs = 0.f;
            #pragma unroll
            for (int j = 0; j < 4; ++j) {
                int ii = i0 - 1 + j;
                float c = (ii >= 0 && ii < PGRID) ? cubicf(fabsf(sf - (float)ii)) : 0.f;
                w[j] = c; cs += c;
            }
            float inv = __fdividef(1.0f, cs);
            #pragma unroll
            for (int j = 0; j < 4; ++j) {
                int ii = i0 - 1 + j;
                if (ii >= 0 && ii < PGRID && w[j] != 0.f)
                    atomicAdd(&dst[ii], w[j] * inv);
            }
        }
        __syncthreads();
        if (t < PGRID)            g_vy[bn*PGRID + t]           = sv[t];
        else if (t < 2*PGRID)     g_vx[bn*PGRID + (t - PGRID)] = sv[t];

        if (t == 0) {
            float sfl = (y_min + 0.5f) * (1.0f/14.0f) - 0.5f;
            float sfh = (y_max - 2 + 0.5f) * (1.0f/14.0f) - 0.5f;
            int p0 = max(0, (int)floorf(sfl) - 1);
            int p1 = min(PGRID - 1, (int)floorf(sfh) + 2);
            sfl = (x_min + 0.5f) * (1.0f/14.0f) - 0.5f;
            sfh = (x_max - 2 + 0.5f) * (1.0f/14.0f) - 0.5f;
            int q0 = max(0, (int)floorf(sfl) - 1);
            int q1 = min(PGRID - 1, (int)floorf(sfh) + 2);
            g_rect[bn*4+0] = p0; g_rect[bn*4+1] = p1;
            g_rect[bn*4+2] = q0; g_rect[bn*4+3] = q1;
            g_cntinv[bn] = __fdividef(1.0f, (float)(ny * nx));
        }
    }
}

// ---------------- kernel 2: Q[bn,d] = sum_k w[bn,k]/fn[b,k] * feats[b,k,d] ------
__global__ void __launch_bounds__(256) q_kernel(const float* __restrict__ feats) {
    int s  = blockIdx.x;       // 0..QSPLIT-1
    int bn = blockIdx.y;       // 0..63
    int b  = bn >> 5;
    int t  = threadIdx.x;

    __shared__ int   rect[4];
    __shared__ float vxs[16];
    if (t < 4) rect[t] = g_rect[bn*4+t];
    __syncthreads();
    int p0 = rect[0], p1 = rect[1], q0 = rect[2], q1 = rect[3];
    int nq = q1 - q0 + 1;      // <= 15
    if (t < 16) vxs[t] = (t < nq) ? g_vx[bn*PGRID + q0 + t] : 0.f;
    __syncthreads();

    int np  = p1 - p0 + 1;
    int plo = p0 + (np * s) / QSPLIT;
    int phi = p0 + (np * (s + 1)) / QSPLIT - 1;

    float4 acc = make_float4(0.f, 0.f, 0.f, 0.f);
    const float4* f4 = (const float4*)feats;

    for (int p = plo; p <= phi; ++p) {
        float wy = g_vy[bn*PGRID + p];
        int kbase = b*KPATCH + p*PGRID + q0;
        #pragma unroll
        for (int j = 0; j < 16; ++j) {
            int jj = min(j, nq - 1);                  // clamp address, weight is 0
            float w = wy * vxs[j] * g_fninv[kbase + jj];
            float4 f = f4[(size_t)(kbase + jj) * (DDIM/4) + t];
            acc.x += w * f.x; acc.y += w * f.y;
            acc.z += w * f.z; acc.w += w * f.w;
        }
    }
    ((float4*)g_Qpart)[(size_t)(s*BN + bn) * (DDIM/4) + t] = acc;
}

// ---------------- kernel 3: out += (Q @ embT) * cntinv  (atomic d-split) --------
__global__ void __launch_bounds__(256) out_kernel(const float* __restrict__ emb,
                                                  float* __restrict__ out) {
    __shared__ float Qs[BN * 64];      // [bn][dd]  16KB
    __shared__ float Es[32 * 68];      // [c][dd]   8.5KB, stride 68
    int c0 = blockIdx.x * 32;
    int d0 = blockIdx.y * 64;
    int t  = threadIdx.x;

    const float4* qp4 = (const float4*)g_Qpart;
    #pragma unroll
    for (int i = 0; i < 4; ++i) {
        int lin = i * 256 + t;                 // 0..1023
        int bn = lin >> 4, dd4 = lin & 15;
        float4 v = make_float4(0.f,0.f,0.f,0.f);
        #pragma unroll
        for (int sp = 0; sp < QSPLIT; ++sp) {
            float4 a = qp4[(size_t)(sp*BN + bn) * (DDIM/4) + (d0>>2) + dd4];
            v.x += a.x; v.y += a.y; v.z += a.z; v.w += a.w;
        }
        ((float4*)Qs)[bn*16 + dd4] = v;
    }
    const float4* e4 = (const float4*)emb;
    #pragma unroll
    for (int i = 0; i < 2; ++i) {
        int lin = i * 256 + t;                 // 0..511
        int c = lin >> 4, dd4 = lin & 15;
        float s = g_eninv[c0 + c];
        float4 a = e4[(size_t)(c0 + c) * (DDIM/4) + (d0>>2) + dd4];
        a.x *= s; a.y *= s; a.z *= s; a.w *= s;
        *(float4*)&Es[c*68 + dd4*4] = a;
    }
    __syncthreads();

    int c = t & 31, g = t >> 5;        // 8 bn-groups of 8
    float acc[8] = {0,0,0,0,0,0,0,0};
    #pragma unroll
    for (int dd4 = 0; dd4 < 16; ++dd4) {
        float4 e = *(const float4*)&Es[c*68 + dd4*4];
        #pragma unroll
        for (int j = 0; j < 8; ++j) {
            float4 q = ((const float4*)Qs)[(g*8 + j)*16 + dd4];   // broadcast
            acc[j] += q.x*e.x + q.y*e.y + q.z*e.z + q.w*e.w;
        }
    }
    #pragma unroll
    for (int j = 0; j < 8; ++j) {
        int bn = g*8 + j;
        atomicAdd(&out[bn*CCLS + c0 + c], acc[j] * g_cntinv[bn]);
    }
}

// ---------------- launch --------------------------------------------------------
extern "C" void kernel_launch(void* const* d_in, const int* in_sizes, int n_in,
                              void* d_out, int out_size) {
    (void)in_sizes; (void)n_in; (void)out_size;
    const float* feats = (const float*)d_in[0];
    const float* emb   = (const float*)d_in[1];
    const int*   boxes = (const int*)d_in[2];
    float* out = (float*)d_out;

    normbox_kernel<<<BN + ZEROBLKS + NORMBLKS, 256>>>(feats, emb, boxes, out);
    q_kernel<<<dim3(QSPLIT, BN), 256>>>(feats);
    out_kernel<<<dim3(CCLS/32, DDIM/64), 256>>>(emb, out);
}

// round 7
// speedup vs baseline: 1.1139x; 1.1139x over previous
#include <cuda_runtime.h>
#include <math.h>

#define BATCH  2
#define KPATCH 1600
#define DDIM   1024
#define CCLS   256
#define NBOX   32
#define PGRID  40
#define TARGET 560
#define BN     (BATCH*NBOX)            /* 64 */
#define NROWS  (BATCH*KPATCH + CCLS)   /* 3456 norm rows */
#define ZEROBLKS 4
#define QSPLIT 4
#define NBLOCKS 256                    /* must all be co-resident: 148 SM x 2 */

// ---------------- scratch (static device globals; no allocation) ----------------
__device__ float g_fninv[BATCH*KPATCH];
__device__ float g_eninv[CCLS];
__device__ float g_vy[BN*PGRID];
__device__ float g_vx[BN*PGRID];
__device__ int   g_rect[BN*4];
__device__ float g_cntinv[BN];
__device__ float g_Qpart[QSPLIT*BN*DDIM];

// grid barrier state (sense-reversal; self-resetting across graph replays)
__device__ unsigned g_bar_count = 0;
__device__ volatile unsigned g_bar_gen = 0;

__device__ __forceinline__ void grid_barrier() {
    __syncthreads();
    if (threadIdx.x == 0) {
        __threadfence();                       // publish this block's writes
        unsigned gen = g_bar_gen;
        unsigned old = atomicAdd(&g_bar_count, 1);
        if (old == NBLOCKS - 1) {
            g_bar_count = 0;
            __threadfence();
            g_bar_gen = gen + 1;               // release
        } else {
            while (g_bar_gen == gen) { __nanosleep(32); }
        }
        __threadfence();                       // acquire
    }
    __syncthreads();
}

// Keys cubic, a = -0.5 (matches jax.image.resize 'bicubic')
__device__ __forceinline__ float cubicf(float x) {   // x >= 0
    if (x < 1.f) return ((1.5f*x - 2.5f)*x)*x + 1.f;
    if (x < 2.f) return ((-0.5f*x + 2.5f)*x - 4.f)*x + 2.f;
    return 0.f;
}

// ---------------- the single fused kernel --------------------------------------
__global__ void __launch_bounds__(256, 2) fused_kernel(
        const float* __restrict__ feats,
        const float* __restrict__ emb,
        const int* __restrict__ boxes,
        float* __restrict__ out) {
    __shared__ union {
        struct { float sv[2*PGRID]; } a;                 // box taps
        struct { int rect[4]; float vxs[16]; } b;        // Q phase
        struct { float Qs[64*64]; float Es[32*68]; } c;  // GEMM phase (24.7KB)
    } sm;

    int blk  = blockIdx.x;
    int t    = threadIdx.x;
    int warp = t >> 5, lane = t & 31;

    // ================= Phase A: norms + box taps + zero out ====================
    // warp-per-row norms, MLP=8; 2048 warps cover 3456 rows in <=2 iterations
    for (int row = blk*8 + warp; row < NROWS; row += NBLOCKS*8) {
        const float4* p4 = (row < BATCH*KPATCH)
                 ? (const float4*)(feats + (size_t)row * DDIM)
                 : (const float4*)(emb   + (size_t)(row - BATCH*KPATCH) * DDIM);
        float4 v[8];
        #pragma unroll
        for (int i = 0; i < 8; ++i) v[i] = p4[lane + 32*i];
        float ss = 0.f;
        #pragma unroll
        for (int i = 0; i < 8; ++i)
            ss += v[i].x*v[i].x + v[i].y*v[i].y + v[i].z*v[i].z + v[i].w*v[i].w;
        #pragma unroll
        for (int o = 16; o; o >>= 1) ss += __shfl_xor_sync(0xffffffffu, ss, o);
        if (lane == 0) {
            float inv = 1.0f / sqrtf(ss);
            if (row < BATCH*KPATCH) g_fninv[row] = inv;
            else                    g_eninv[row - BATCH*KPATCH] = inv;
        }
    }

    if (blk < BN) {
        // box branch: per-pixel-parallel bicubic tap accumulation
        int bn = blk;
        int x_min = boxes[bn*4+0], y_min = boxes[bn*4+1];
        int x_max = boxes[bn*4+2], y_max = boxes[bn*4+3];
        __syncthreads();                       // norms done touching nothing shared
        if (t < 2*PGRID) sm.a.sv[t] = 0.f;
        __syncthreads();
        int ny = y_max - 1 - y_min;
        int nx = x_max - 1 - x_min;
        for (int i = t; i < ny + nx; i += 256) {
            int y; float* dst;
            if (i < ny) { y = y_min + i;        dst = sm.a.sv; }
            else        { y = x_min + (i - ny); dst = sm.a.sv + PGRID; }
            float sf = (y + 0.5f) * (1.0f/14.0f) - 0.5f;
            int i0 = (int)floorf(sf);
            float w[4]; float cs = 0.f;
            #pragma unroll
            for (int j = 0; j < 4; ++j) {
                int ii = i0 - 1 + j;
                float c = (ii >= 0 && ii < PGRID) ? cubicf(fabsf(sf - (float)ii)) : 0.f;
                w[j] = c; cs += c;
            }
            float inv = __fdividef(1.0f, cs);
            #pragma unroll
            for (int j = 0; j < 4; ++j) {
                int ii = i0 - 1 + j;
                if (ii >= 0 && ii < PGRID && w[j] != 0.f)
                    atomicAdd(&dst[ii], w[j] * inv);
            }
        }
        __syncthreads();
        if (t < PGRID)        g_vy[bn*PGRID + t]           = sm.a.sv[t];
        else if (t < 2*PGRID) g_vx[bn*PGRID + (t - PGRID)] = sm.a.sv[t];
        if (t == 0) {
            float sfl = (y_min + 0.5f) * (1.0f/14.0f) - 0.5f;
            float sfh = (y_max - 2 + 0.5f) * (1.0f/14.0f) - 0.5f;
            int p0 = max(0, (int)floorf(sfl) - 1);
            int p1 = min(PGRID - 1, (int)floorf(sfh) + 2);
            sfl = (x_min + 0.5f) * (1.0f/14.0f) - 0.5f;
            sfh = (x_max - 2 + 0.5f) * (1.0f/14.0f) - 0.5f;
            int q0 = max(0, (int)floorf(sfl) - 1);
            int q1 = min(PGRID - 1, (int)floorf(sfh) + 2);
            g_rect[bn*4+0] = p0; g_rect[bn*4+1] = p1;
            g_rect[bn*4+2] = q0; g_rect[bn*4+3] = q1;
            g_cntinv[bn] = __fdividef(1.0f, (float)(ny * nx));
        }
    } else if (blk < BN + ZEROBLKS) {
        // zero the 64KB output so phase C can atomically accumulate
        int zb = blk - BN;
        float4 z = make_float4(0.f, 0.f, 0.f, 0.f);
        #pragma unroll
        for (int i = 0; i < 4; ++i)
            ((float4*)out)[(zb * 256 + t) * 4 + i] = z;
    }

    grid_barrier();   // ======== norms, taps, rects, zeroed out all visible ======

    // ================= Phase B: Q[bn,d] partials (one (s,bn) per block) ========
    {
        int bn = blk & 63, s = blk >> 6, b = bn >> 5;
        if (t < 4) sm.b.rect[t] = g_rect[bn*4+t];
        __syncthreads();
        int p0 = sm.b.rect[0], p1 = sm.b.rect[1];
        int q0 = sm.b.rect[2], q1 = sm.b.rect[3];
        int nq = q1 - q0 + 1;                  // <= 15
        if (t < 16) sm.b.vxs[t] = (t < nq) ? g_vx[bn*PGRID + q0 + t] : 0.f;
        __syncthreads();

        int np  = p1 - p0 + 1;
        int plo = p0 + (np * s) / QSPLIT;
        int phi = p0 + (np * (s + 1)) / QSPLIT - 1;

        float4 acc = make_float4(0.f, 0.f, 0.f, 0.f);
        const float4* f4 = (const float4*)feats;
        for (int p = plo; p <= phi; ++p) {
            float wy = g_vy[bn*PGRID + p];
            int kbase = b*KPATCH + p*PGRID + q0;
            #pragma unroll
            for (int j = 0; j < 16; ++j) {
                int jj = min(j, nq - 1);       // clamp address; weight is 0 beyond
                float w = wy * sm.b.vxs[j] * g_fninv[kbase + jj];
                float4 f = f4[(size_t)(kbase + jj) * (DDIM/4) + t];
                acc.x += w * f.x; acc.y += w * f.y;
                acc.z += w * f.z; acc.w += w * f.w;
            }
        }
        ((float4*)g_Qpart)[(size_t)(s*BN + bn) * (DDIM/4) + t] = acc;
    }

    grid_barrier();   // ======== Qpart complete ==================================

    // ================= Phase C: out += (Q @ embT) * cntinv (blocks 0..127) =====
    if (blk < 128) {
        int c0 = (blk & 7) * 32;
        int d0 = (blk >> 3) * 64;

        const float4* qp4 = (const float4*)g_Qpart;
        #pragma unroll
        for (int i = 0; i < 4; ++i) {
            int lin = i * 256 + t;             // 0..1023
            int bn = lin >> 4, dd4 = lin & 15;
            float4 v = make_float4(0.f,0.f,0.f,0.f);
            #pragma unroll
            for (int sp = 0; sp < QSPLIT; ++sp) {
                float4 a = qp4[(size_t)(sp*BN + bn) * (DDIM/4) + (d0>>2) + dd4];
                v.x += a.x; v.y += a.y; v.z += a.z; v.w += a.w;
            }
            ((float4*)sm.c.Qs)[bn*16 + dd4] = v;
        }
        const float4* e4 = (const float4*)emb;
        #pragma unroll
        for (int i = 0; i < 2; ++i) {
            int lin = i * 256 + t;             // 0..511
            int c = lin >> 4, dd4 = lin & 15;
            float s = g_eninv[c0 + c];
            float4 a = e4[(size_t)(c0 + c) * (DDIM/4) + (d0>>2) + dd4];
            a.x *= s; a.y *= s; a.z *= s; a.w *= s;
            *(float4*)&sm.c.Es[c*68 + dd4*4] = a;
        }
        __syncthreads();

        int c = t & 31, g = t >> 5;            // 8 bn-groups of 8
        float acc[8] = {0,0,0,0,0,0,0,0};
        #pragma unroll
        for (int dd4 = 0; dd4 < 16; ++dd4) {
            float4 e = *(const float4*)&sm.c.Es[c*68 + dd4*4];
            #pragma unroll
            for (int j = 0; j < 8; ++j) {
                float4 q = ((const float4*)sm.c.Qs)[(g*8 + j)*16 + dd4];  // bcast
                acc[j] += q.x*e.x + q.y*e.y + q.z*e.z + q.w*e.w;
            }
        }
        #pragma unroll
        for (int j = 0; j < 8; ++j) {
            int bn = g*8 + j;
            atomicAdd(&out[bn*CCLS + c0 + c], acc[j] * g_cntinv[bn]);
        }
    }
}

// ---------------- launch --------------------------------------------------------
extern "C" void kernel_launch(void* const* d_in, const int* in_sizes, int n_in,
                              void* d_out, int out_size) {
    (void)in_sizes; (void)n_in; (void)out_size;
    const float* feats = (const float*)d_in[0];
    const float* emb   = (const float*)d_in[1];
    const int*   boxes = (const int*)d_in[2];
    float* out = (float*)d_out;

    fused_kernel<<<NBLOCKS, 256>>>(feats, emb, boxes, out);
}

// round 8
// speedup vs baseline: 1.4105x; 1.2662x over previous
#include <cuda_runtime.h>
#include <math.h>

#define BATCH  2
#define KPATCH 1600
#define DDIM   1024
#define CCLS   256
#define NBOX   32
#define PGRID  40
#define TARGET 560
#define BN     (BATCH*NBOX)            /* 64 */
#define QSPLIT 4

// ---------------- scratch (static device globals; no allocation) ----------------
__device__ float g_eninv[CCLS];             // 1/||emb[c,:]||
__device__ float g_cntinv[BN];              // 1/(box pixel count)
__device__ float g_Qpart[QSPLIT*BN*DDIM];   // partial weighted feature sums

// Keys cubic, a = -0.5 (matches jax.image.resize 'bicubic')
__device__ __forceinline__ float cubicf(float x) {   // x >= 0
    if (x < 1.f) return ((1.5f*x - 2.5f)*x)*x + 1.f;
    if (x < 2.f) return ((-0.5f*x + 2.5f)*x - 4.f)*x + 2.f;
    return 0.f;
}

// ---------------- kernel 1: Q partials with inline norms ------------------------
// grid (QSPLIT+1, BN).  s<QSPLIT: Q work for (s,bn).  s==QSPLIT: misc block bn
// (4 embedding norms + zero 256 floats of out).
// Q block: computes box bn's bicubic tap weights in smem (pixel-parallel), then
// warp-per-tap: load full 1024-d feature row (MLP=8), warp-reduce sumsq for the
// inline 1/||f||, accumulate w*f into per-warp float4 acc, block-reduce at end.
__global__ void __launch_bounds__(256) q_kernel(
        const float* __restrict__ feats,
        const float* __restrict__ emb,
        const int* __restrict__ boxes,
        float* __restrict__ out) {
    int s    = blockIdx.x;
    int bn   = blockIdx.y;
    int t    = threadIdx.x;
    int warp = t >> 5, lane = t & 31;

    if (s == QSPLIT) {
        // ---- misc: 4 emb-row norms (2 warps per row, MLP=4) + zero out slice ---
        __shared__ float ws[8];
        int row  = bn * 4 + (warp >> 1);
        int half = warp & 1;
        const float4* p4 = (const float4*)(emb) + (size_t)row * 256 + half * 128;
        float4 v[4];
        #pragma unroll
        for (int i = 0; i < 4; ++i) v[i] = p4[lane + 32*i];
        float ss = 0.f;
        #pragma unroll
        for (int i = 0; i < 4; ++i)
            ss += v[i].x*v[i].x + v[i].y*v[i].y + v[i].z*v[i].z + v[i].w*v[i].w;
        #pragma unroll
        for (int o = 16; o; o >>= 1) ss += __shfl_xor_sync(0xffffffffu, ss, o);
        if (lane == 0) ws[warp] = ss;
        // zero this block's 256-float slice of out (64 bn * 256 c total)
        out[bn * CCLS + t] = 0.f;
        __syncthreads();
        if (t < 4)
            g_eninv[bn*4 + t] = 1.0f / sqrtf(ws[2*t] + ws[2*t+1]);
        return;
    }

    // ---------------- box tap weights in shared memory -------------------------
    __shared__ float sv[2*PGRID];              // vy[0..39], vx[40..79]
    __shared__ float red[8 * DDIM];            // per-warp Q partials (32KB)

    int x_min = boxes[bn*4+0], y_min = boxes[bn*4+1];
    int x_max = boxes[bn*4+2], y_max = boxes[bn*4+3];
    if (t < 2*PGRID) sv[t] = 0.f;
    __syncthreads();

    int ny = y_max - 1 - y_min;
    int nx = x_max - 1 - x_min;
    for (int i = t; i < ny + nx; i += 256) {
        int y; float* dst;
        if (i < ny) { y = y_min + i;        dst = sv; }
        else        { y = x_min + (i - ny); dst = sv + PGRID; }
        float sf = (y + 0.5f) * (1.0f/14.0f) - 0.5f;
        int i0 = (int)floorf(sf);
        float w[4]; float cs = 0.f;
        #pragma unroll
        for (int j = 0; j < 4; ++j) {
            int ii = i0 - 1 + j;
            float c = (ii >= 0 && ii < PGRID) ? cubicf(fabsf(sf - (float)ii)) : 0.f;
            w[j] = c; cs += c;
        }
        float inv = __fdividef(1.0f, cs);
        #pragma unroll
        for (int j = 0; j < 4; ++j) {
            int ii = i0 - 1 + j;
            if (ii >= 0 && ii < PGRID && w[j] != 0.f)
                atomicAdd(&dst[ii], w[j] * inv);
        }
    }
    if (t == 0 && s == 0)
        g_cntinv[bn] = __fdividef(1.0f, (float)(ny * nx));
    __syncthreads();

    // ---------------- tap rectangle + this block's p slice ---------------------
    float sfl = (y_min + 0.5f) * (1.0f/14.0f) - 0.5f;
    float sfh = (y_max - 2 + 0.5f) * (1.0f/14.0f) - 0.5f;
    int p0 = max(0, (int)floorf(sfl) - 1);
    int p1 = min(PGRID - 1, (int)floorf(sfh) + 2);
    sfl = (x_min + 0.5f) * (1.0f/14.0f) - 0.5f;
    sfh = (x_max - 2 + 0.5f) * (1.0f/14.0f) - 0.5f;
    int q0 = max(0, (int)floorf(sfl) - 1);
    int q1 = min(PGRID - 1, (int)floorf(sfh) + 2);
    int nq = q1 - q0 + 1;

    int np  = p1 - p0 + 1;
    int plo = p0 + (np * s) / QSPLIT;
    int phi = p0 + (np * (s + 1)) / QSPLIT - 1;
    int b   = bn >> 5;

    // ---------------- warp-per-tap accumulation with inline norm ---------------
    float4 acc[8];
    #pragma unroll
    for (int i = 0; i < 8; ++i) acc[i] = make_float4(0.f,0.f,0.f,0.f);

    int ntaps = (phi - plo + 1) * nq;
    const float4* f4 = (const float4*)feats;
    for (int tw = warp; tw < ntaps; tw += 8) {
        int pi = tw / nq;
        int qi = tw - pi * nq;
        int p  = plo + pi, q = q0 + qi;
        const float4* row = f4 + (size_t)(b*KPATCH + p*PGRID + q) * 256;
        float4 v[8];
        #pragma unroll
        for (int i = 0; i < 8; ++i) v[i] = row[lane + 32*i];   // MLP=8
        float ss = 0.f;
        #pragma unroll
        for (int i = 0; i < 8; ++i)
            ss += v[i].x*v[i].x + v[i].y*v[i].y + v[i].z*v[i].z + v[i].w*v[i].w;
        #pragma unroll
        for (int o = 16; o; o >>= 1) ss += __shfl_xor_sync(0xffffffffu, ss, o);
        float w = sv[p] * sv[PGRID + q] * (1.0f / sqrtf(ss));
        #pragma unroll
        for (int i = 0; i < 8; ++i) {
            acc[i].x += w * v[i].x; acc[i].y += w * v[i].y;
            acc[i].z += w * v[i].z; acc[i].w += w * v[i].w;
        }
    }

    // ---------------- block reduce over 8 warps --------------------------------
    #pragma unroll
    for (int i = 0; i < 8; ++i)
        ((float4*)red)[warp*256 + lane + 32*i] = acc[i];
    __syncthreads();
    float4 sum = make_float4(0.f,0.f,0.f,0.f);
    #pragma unroll
    for (int w = 0; w < 8; ++w) {
        float4 a = ((const float4*)red)[w*256 + t];
        sum.x += a.x; sum.y += a.y; sum.z += a.z; sum.w += a.w;
    }
    ((float4*)g_Qpart)[(size_t)(s*BN + bn) * 256 + t] = sum;
}

// ---------------- kernel 2: out += (Q @ embT) * cntinv  (atomic d-split) --------
__global__ void __launch_bounds__(256) out_kernel(const float* __restrict__ emb,
                                                  float* __restrict__ out) {
    __shared__ float Qs[BN * 64];      // [bn][dd]  16KB
    __shared__ float Es[32 * 68];      // [c][dd]   8.5KB, stride 68
    int c0 = blockIdx.x * 32;
    int d0 = blockIdx.y * 64;
    int t  = threadIdx.x;

    const float4* qp4 = (const float4*)g_Qpart;
    #pragma unroll
    for (int i = 0; i < 4; ++i) {
        int lin = i * 256 + t;                 // 0..1023
        int bn = lin >> 4, dd4 = lin & 15;
        float4 v = make_float4(0.f,0.f,0.f,0.f);
        #pragma unroll
        for (int sp = 0; sp < QSPLIT; ++sp) {
            float4 a = qp4[(size_t)(sp*BN + bn) * 256 + (d0>>2) + dd4];
            v.x += a.x; v.y += a.y; v.z += a.z; v.w += a.w;
        }
        ((float4*)Qs)[bn*16 + dd4] = v;
    }
    const float4* e4 = (const float4*)emb;
    #pragma unroll
    for (int i = 0; i < 2; ++i) {
        int lin = i * 256 + t;                 // 0..511
        int c = lin >> 4, dd4 = lin & 15;
        float sc = g_eninv[c0 + c];
        float4 a = e4[(size_t)(c0 + c) * 256 + (d0>>2) + dd4];
        a.x *= sc; a.y *= sc; a.z *= sc; a.w *= sc;
        *(float4*)&Es[c*68 + dd4*4] = a;
    }
    __syncthreads();

    int c = t & 31, g = t >> 5;            // 8 bn-groups of 8
    float acc[8] = {0,0,0,0,0,0,0,0};
    #pragma unroll
    for (int dd4 = 0; dd4 < 16; ++dd4) {
        float4 e = *(const float4*)&Es[c*68 + dd4*4];
        #pragma unroll
        for (int j = 0; j < 8; ++j) {
            float4 q = ((const float4*)Qs)[(g*8 + j)*16 + dd4];   // broadcast
            acc[j] += q.x*e.x + q.y*e.y + q.z*e.z + q.w*e.w;
        }
    }
    #pragma unroll
    for (int j = 0; j < 8; ++j) {
        int bn = g*8 + j;
        atomicAdd(&out[bn*CCLS + c0 + c], acc[j] * g_cntinv[bn]);
    }
}

// ---------------- launch --------------------------------------------------------
extern "C" void kernel_launch(void* const* d_in, const int* in_sizes, int n_in,
                              void* d_out, int out_size) {
    (void)in_sizes; (void)n_in; (void)out_size;
    const float* feats = (const float*)d_in[0];
    const float* emb   = (const float*)d_in[1];
    const int*   boxes = (const int*)d_in[2];
    float* out = (float*)d_out;

    q_kernel<<<dim3(QSPLIT + 1, BN), 256>>>(feats, emb, boxes, out);
    out_kernel<<<dim3(CCLS/32, DDIM/64), 256>>>(emb, out);
}

// round 9
// speedup vs baseline: 1.4378x; 1.0194x over previous
#include <cuda_runtime.h>
#include <math.h>

#define BATCH  2
#define KPATCH 1600
#define DDIM   1024
#define CCLS   256
#define NBOX   32
#define PGRID  40
#define TARGET 560
#define BN     (BATCH*NBOX)            /* 64 */
#define QSPLIT 4

// ---------------- scratch (static device globals; no allocation) ----------------
__device__ float g_eninv[CCLS];             // 1/||emb[c,:]||
__device__ float g_cntinv[BN];              // 1/(box pixel count)
__device__ float g_Qpart[QSPLIT*BN*DDIM];   // partial weighted feature sums

// Keys cubic, a = -0.5 (matches jax.image.resize 'bicubic')
__device__ __forceinline__ float cubicf(float x) {   // x >= 0
    if (x < 1.f) return ((1.5f*x - 2.5f)*x)*x + 1.f;
    if (x < 2.f) return ((-0.5f*x + 2.5f)*x - 4.f)*x + 2.f;
    return 0.f;
}

// ---------------- kernel 1: Q partials with inline norms ------------------------
// grid (QSPLIT+1, BN).  s<QSPLIT: Q work for (s,bn).  s==QSPLIT: misc block bn
// (4 embedding norms + zero 256 floats of out).
// Q block: box tap weights in smem (pixel-parallel), then warp-per-tap-PAIR:
// two full 1024-d rows in flight per warp (16 LDG.128, interleaved shfl chains).
__global__ void __launch_bounds__(256) q_kernel(
        const float* __restrict__ feats,
        const float* __restrict__ emb,
        const int* __restrict__ boxes,
        float* __restrict__ out) {
    int s    = blockIdx.x;
    int bn   = blockIdx.y;
    int t    = threadIdx.x;
    int warp = t >> 5, lane = t & 31;

    if (s == QSPLIT) {
        // ---- misc: 4 emb-row norms (2 warps per row, MLP=4) + zero out slice ---
        __shared__ float ws[8];
        int row  = bn * 4 + (warp >> 1);
        int half = warp & 1;
        const float4* p4 = (const float4*)(emb) + (size_t)row * 256 + half * 128;
        float4 v[4];
        #pragma unroll
        for (int i = 0; i < 4; ++i) v[i] = p4[lane + 32*i];
        float ss = 0.f;
        #pragma unroll
        for (int i = 0; i < 4; ++i)
            ss += v[i].x*v[i].x + v[i].y*v[i].y + v[i].z*v[i].z + v[i].w*v[i].w;
        #pragma unroll
        for (int o = 16; o; o >>= 1) ss += __shfl_xor_sync(0xffffffffu, ss, o);
        if (lane == 0) ws[warp] = ss;
        out[bn * CCLS + t] = 0.f;              // zero out (64 blocks x 256 = all)
        __syncthreads();
        if (t < 4)
            g_eninv[bn*4 + t] = 1.0f / sqrtf(ws[2*t] + ws[2*t+1]);
        return;
    }

    // ---------------- box tap weights in shared memory -------------------------
    __shared__ float sv[2*PGRID];              // vy[0..39], vx[40..79]
    __shared__ float red[8 * DDIM];            // per-warp Q partials (32KB)

    int x_min = boxes[bn*4+0], y_min = boxes[bn*4+1];
    int x_max = boxes[bn*4+2], y_max = boxes[bn*4+3];
    if (t < 2*PGRID) sv[t] = 0.f;
    __syncthreads();

    int ny = y_max - 1 - y_min;
    int nx = x_max - 1 - x_min;
    for (int i = t; i < ny + nx; i += 256) {
        int y; float* dst;
        if (i < ny) { y = y_min + i;        dst = sv; }
        else        { y = x_min + (i - ny); dst = sv + PGRID; }
        float sf = (y + 0.5f) * (1.0f/14.0f) - 0.5f;
        int i0 = (int)floorf(sf);
        float w[4]; float cs = 0.f;
        #pragma unroll
        for (int j = 0; j < 4; ++j) {
            int ii = i0 - 1 + j;
            float c = (ii >= 0 && ii < PGRID) ? cubicf(fabsf(sf - (float)ii)) : 0.f;
            w[j] = c; cs += c;
        }
        float inv = __fdividef(1.0f, cs);
        #pragma unroll
        for (int j = 0; j < 4; ++j) {
            int ii = i0 - 1 + j;
            if (ii >= 0 && ii < PGRID && w[j] != 0.f)
                atomicAdd(&dst[ii], w[j] * inv);
        }
    }
    if (t == 0 && s == 0)
        g_cntinv[bn] = __fdividef(1.0f, (float)(ny * nx));
    __syncthreads();

    // ---------------- tap rectangle + this block's p slice ---------------------
    float sfl = (y_min + 0.5f) * (1.0f/14.0f) - 0.5f;
    float sfh = (y_max - 2 + 0.5f) * (1.0f/14.0f) - 0.5f;
    int p0 = max(0, (int)floorf(sfl) - 1);
    int p1 = min(PGRID - 1, (int)floorf(sfh) + 2);
    sfl = (x_min + 0.5f) * (1.0f/14.0f) - 0.5f;
    sfh = (x_max - 2 + 0.5f) * (1.0f/14.0f) - 0.5f;
    int q0 = max(0, (int)floorf(sfl) - 1);
    int q1 = min(PGRID - 1, (int)floorf(sfh) + 2);
    int nq = q1 - q0 + 1;

    int np  = p1 - p0 + 1;
    int plo = p0 + (np * s) / QSPLIT;
    int phi = p0 + (np * (s + 1)) / QSPLIT - 1;
    int b   = bn >> 5;

    // ---------------- warp-per-tap-pair accumulation with inline norms ---------
    float4 acc[8];
    #pragma unroll
    for (int i = 0; i < 8; ++i) acc[i] = make_float4(0.f,0.f,0.f,0.f);

    int ntaps = (phi - plo + 1) * nq;
    const float4* f4 = (const float4*)feats;
    for (int tw = warp * 2; tw < ntaps; tw += 16) {
        int tw1  = min(tw + 1, ntaps - 1);
        bool has1 = (tw + 1 < ntaps);
        int pi0 = tw  / nq, qi0 = tw  - pi0*nq;
        int pi1 = tw1 / nq, qi1 = tw1 - pi1*nq;
        int pA = plo + pi0, qA = q0 + qi0;
        int pB = plo + pi1, qB = q0 + qi1;
        const float4* r0 = f4 + (size_t)(b*KPATCH + pA*PGRID + qA) * 256;
        const float4* r1 = f4 + (size_t)(b*KPATCH + pB*PGRID + qB) * 256;
        float4 v0[8], v1[8];
        #pragma unroll
        for (int i = 0; i < 8; ++i) v0[i] = r0[lane + 32*i];   // 16 independent
        #pragma unroll
        for (int i = 0; i < 8; ++i) v1[i] = r1[lane + 32*i];   // LDG.128 in flight
        float s0 = 0.f, s1 = 0.f;
        #pragma unroll
        for (int i = 0; i < 8; ++i) {
            s0 += v0[i].x*v0[i].x + v0[i].y*v0[i].y + v0[i].z*v0[i].z + v0[i].w*v0[i].w;
            s1 += v1[i].x*v1[i].x + v1[i].y*v1[i].y + v1[i].z*v1[i].z + v1[i].w*v1[i].w;
        }
        #pragma unroll
        for (int o = 16; o; o >>= 1) {                          // interleaved chains
            s0 += __shfl_xor_sync(0xffffffffu, s0, o);
            s1 += __shfl_xor_sync(0xffffffffu, s1, o);
        }
        float w0 = sv[pA] * sv[PGRID + qA] * (1.0f / sqrtf(s0));
        float w1 = has1 ? sv[pB] * sv[PGRID + qB] * (1.0f / sqrtf(s1)) : 0.f;
        #pragma unroll
        for (int i = 0; i < 8; ++i) {
            acc[i].x += w0 * v0[i].x + w1 * v1[i].x;
            acc[i].y += w0 * v0[i].y + w1 * v1[i].y;
            acc[i].z += w0 * v0[i].z + w1 * v1[i].z;
            acc[i].w += w0 * v0[i].w + w1 * v1[i].w;
        }
    }

    // ---------------- block reduce over 8 warps --------------------------------
    #pragma unroll
    for (int i = 0; i < 8; ++i)
        ((float4*)red)[warp*256 + lane + 32*i] = acc[i];
    __syncthreads();
    float4 sum = make_float4(0.f,0.f,0.f,0.f);
    #pragma unroll
    for (int w = 0; w < 8; ++w) {
        float4 a = ((const float4*)red)[w*256 + t];
        sum.x += a.x; sum.y += a.y; sum.z += a.z; sum.w += a.w;
    }
    ((float4*)g_Qpart)[(size_t)(s*BN + bn) * 256 + t] = sum;
}

// ---------------- kernel 2: out += (Q @ embT) * cntinv  (bn-split, 512 blocks) --
__global__ void __launch_bounds__(256) out_kernel(const float* __restrict__ emb,
                                                  float* __restrict__ out) {
    __shared__ float Qs[16 * 64];      // [bn][dd]  4KB (16-bn slice)
    __shared__ float Es[32 * 68];      // [c][dd]   8.5KB, stride 68
    int c0  = blockIdx.x * 32;
    int d0  = blockIdx.y * 64;
    int bn0 = blockIdx.z * 16;
    int t   = threadIdx.x;

    // Q tile: 256 float4 (16 bn x 16 dd4), one per thread, sum QSPLIT partials
    {
        int bn = t >> 4, dd4 = t & 15;
        const float4* qp4 = (const float4*)g_Qpart;
        float4 v = make_float4(0.f,0.f,0.f,0.f);
        #pragma unroll
        for (int sp = 0; sp < QSPLIT; ++sp) {
            float4 a = qp4[(size_t)(sp*BN + bn0 + bn) * 256 + (d0>>2) + dd4];
            v.x += a.x; v.y += a.y; v.z += a.z; v.w += a.w;
        }
        ((float4*)Qs)[bn*16 + dd4] = v;
    }
    // E tile (512 float4), scaled by 1/||emb_c||
    const float4* e4 = (const float4*)emb;
    #pragma unroll
    for (int i = 0; i < 2; ++i) {
        int lin = i * 256 + t;             // 0..511
        int c = lin >> 4, dd4 = lin & 15;
        float sc = g_eninv[c0 + c];
        float4 a = e4[(size_t)(c0 + c) * 256 + (d0>>2) + dd4];
        a.x *= sc; a.y *= sc; a.z *= sc; a.w *= sc;
        *(float4*)&Es[c*68 + dd4*4] = a;
    }
    __syncthreads();

    int c = t & 31, g = t >> 5;            // 8 groups x 2 bn each
    float acc[2] = {0.f, 0.f};
    #pragma unroll
    for (int dd4 = 0; dd4 < 16; ++dd4) {
        float4 e = *(const float4*)&Es[c*68 + dd4*4];
        #pragma unroll
        for (int j = 0; j < 2; ++j) {
            float4 q = ((const float4*)Qs)[(g*2 + j)*16 + dd4];   // broadcast
            acc[j] += q.x*e.x + q.y*e.y + q.z*e.z + q.w*e.w;
        }
    }
    #pragma unroll
    for (int j = 0; j < 2; ++j) {
        int bn = bn0 + g*2 + j;
        atomicAdd(&out[bn*CCLS + c0 + c], acc[j] * g_cntinv[bn]);
    }
}

// ---------------- launch --------------------------------------------------------
extern "C" void kernel_launch(void* const* d_in, const int* in_sizes, int n_in,
                              void* d_out, int out_size) {
    (void)in_sizes; (void)n_in; (void)out_size;
    const float* feats = (const float*)d_in[0];
    const float* emb   = (const float*)d_in[1];
    const int*   boxes = (const int*)d_in[2];
    float* out = (float*)d_out;

    q_kernel<<<dim3(QSPLIT + 1, BN), 256>>>(feats, emb, boxes, out);
    out_kernel<<<dim3(CCLS/32, DDIM/64, BN/16), 256>>>(emb, out);
}